// round 6
// baseline (speedup 1.0000x reference)
#include <cuda_runtime.h>
#include <stdint.h>

#define BATCH 32
#define NPOS  8732
#define CLS_OFF ((size_t)BATCH * NPOS * 4)
#define QMAX 16256.0f
#define INV2 (1.0f / (16256.0f * 16256.0f))

// static scratch
__device__ int8_t  g_qa_hi[37412864];
__device__ int8_t  g_qa_lo[37412864];
__device__ int8_t  g_qw_hi[12695040];
__device__ int8_t  g_qw_lo[12695040];
__device__ float    g_sw[2850];
__device__ unsigned g_sAbits[6];

__device__ __forceinline__ uint32_t smem_u32(const void* p) {
    uint32_t r;
    asm("{ .reg .u64 t; cvta.to.shared.u64 t, %1; cvt.u32.u64 %0, t; }" : "=r"(r) : "l"(p));
    return r;
}
__device__ __forceinline__ void cp16(uint32_t dst, const void* src, uint32_t sz) {
    asm volatile("cp.async.cg.shared.global [%0], [%1], 16, %2;"
                 :: "r"(dst), "l"(src), "r"(sz) : "memory");
}
__device__ __forceinline__ void cp_commit() { asm volatile("cp.async.commit_group;" ::: "memory"); }
__device__ __forceinline__ void cp_wait2()  { asm volatile("cp.async.wait_group 2;" ::: "memory"); }
__device__ __forceinline__ void cp_wait1()  { asm volatile("cp.async.wait_group 1;" ::: "memory"); }
__device__ __forceinline__ void cp_wait0()  { asm volatile("cp.async.wait_group 0;" ::: "memory"); }
__device__ __forceinline__ void ldsm4(uint32_t* r, uint32_t a) {
    asm volatile("ldmatrix.sync.aligned.m8n8.x4.shared.b16 {%0,%1,%2,%3}, [%4];"
                 : "=r"(r[0]), "=r"(r[1]), "=r"(r[2]), "=r"(r[3]) : "r"(a));
}
__device__ __forceinline__ void mma_s8(int* d, const uint32_t* a, uint32_t b0, uint32_t b1) {
    asm volatile("mma.sync.aligned.m16n8k32.row.col.s32.s8.s8.s32 "
                 "{%0,%1,%2,%3}, {%4,%5,%6,%7}, {%8,%9}, {%0,%1,%2,%3};"
                 : "+r"(d[0]), "+r"(d[1]), "+r"(d[2]), "+r"(d[3])
                 : "r"(a[0]), "r"(a[1]), "r"(a[2]), "r"(a[3]), "r"(b0), "r"(b1));
}

__global__ void zero_sa_kernel() { if (threadIdx.x < 6) g_sAbits[threadIdx.x] = 0u; }

// per-level activation amax
__global__ void amax_x_kernel(const float* __restrict__ x, int total, int lvl) {
    __shared__ float red[8];
    float m = 0.f;
    for (int i = blockIdx.x * blockDim.x + threadIdx.x; i < total; i += gridDim.x * blockDim.x)
        m = fmaxf(m, fabsf(x[i]));
#pragma unroll
    for (int o = 16; o; o >>= 1) m = fmaxf(m, __shfl_xor_sync(~0u, m, o));
    if ((threadIdx.x & 31) == 0) red[threadIdx.x >> 5] = m;
    __syncthreads();
    if (threadIdx.x < 8) {
        m = red[threadIdx.x];
#pragma unroll
        for (int o = 4; o; o >>= 1) m = fmaxf(m, __shfl_xor_sync(0xFF, m, o));
        if (threadIdx.x == 0) atomicMax(&g_sAbits[lvl], __float_as_uint(m));
    }
}

// transpose [n][c][p] -> [n][p][c] + int8 hi/lo quantization
__global__ void transpose_q_kernel(const float* __restrict__ x, size_t xoff,
                                   int C, int HW, int lvl) {
    __shared__ float tile[32][33];
    const int n = blockIdx.z, p0 = blockIdx.x * 32, c0 = blockIdx.y * 32;
    const int tx = threadIdx.x, ty = threadIdx.y;
    const float* xb = x + (size_t)n * C * HW;
    const float inv = QMAX / fmaxf(__uint_as_float(g_sAbits[lvl]), 1e-30f);
#pragma unroll
    for (int k = 0; k < 4; k++) {
        int c = c0 + ty + 8 * k, p = p0 + tx;
        tile[ty + 8 * k][tx] = (p < HW) ? xb[(size_t)c * HW + p] : 0.f;
    }
    __syncthreads();
#pragma unroll
    for (int k = 0; k < 4; k++) {
        int p = p0 + ty + 8 * k, c = c0 + tx;
        if (p < HW) {
            int X = __float2int_rn(tile[tx][ty + 8 * k] * inv);
            int h = (X + 64) >> 7;
            int l = X - (h << 7);
            size_t o = xoff + ((size_t)n * HW + p) * C + c;
            g_qa_hi[o] = (int8_t)h; g_qa_lo[o] = (int8_t)l;
        }
    }
}

// per-output-channel weight amax (o = reg rows then cls rows)
__global__ void wamax_kernel(const float* __restrict__ regw, const float* __restrict__ clsw,
                             size_t swoff, int C, int A4) {
    __shared__ float red[8];
    const int o = blockIdx.x;
    const float* src = (o < A4) ? (regw + (size_t)o * C * 9)
                                : (clsw + (size_t)(o - A4) * C * 9);
    float m = 0.f;
    for (int i = threadIdx.x; i < C * 9; i += blockDim.x) m = fmaxf(m, fabsf(src[i]));
#pragma unroll
    for (int s = 16; s; s >>= 1) m = fmaxf(m, __shfl_xor_sync(~0u, m, s));
    if ((threadIdx.x & 31) == 0) red[threadIdx.x >> 5] = m;
    __syncthreads();
    if (threadIdx.x < 8) {
        m = red[threadIdx.x];
#pragma unroll
        for (int s = 4; s; s >>= 1) m = fmaxf(m, __shfl_xor_sync(0xFF, m, s));
        if (threadIdx.x == 0) g_sw[swoff + o] = m;
    }
}

// weights -> [tap][o][c] int8 hi/lo
__global__ void pack_wq_kernel(const float* __restrict__ regw, const float* __restrict__ clsw,
                               size_t woff, size_t swoff, int C, int A4, int Otot) {
    int idx = blockIdx.x * blockDim.x + threadIdx.x;
    if (idx >= Otot * C) return;
    int c = idx % C, o = idx / C;
    const float* src = (o < A4) ? (regw + ((size_t)o * C + c) * 9)
                                : (clsw + ((size_t)(o - A4) * C + c) * 9);
    const float inv = QMAX / fmaxf(g_sw[swoff + o], 1e-30f);
#pragma unroll
    for (int tap = 0; tap < 9; tap++) {
        int X = __float2int_rn(src[tap] * inv);
        int h = (X + 64) >> 7;
        int l = X - (h << 7);
        size_t d = woff + ((size_t)tap * Otot + o) * C + c;
        g_qw_hi[d] = (int8_t)h; g_qw_lo[d] = (int8_t)l;
    }
}

// ---- main GEMM: int8 mma.m16n8k32 (HH + MM accumulators), CTA 128x128 ----
// k-chunk 64 (int8 bytes), 8 warps 2x4 (warp tile 64x32), 3-stage cp.async.
#define STG 40960
#define ROWB 80

__global__ __launch_bounds__(256, 1)
void gemm_kernel(size_t xoff, size_t woff, size_t swoff, int lvl,
                 const float* __restrict__ regb, const float* __restrict__ clsb,
                 float* __restrict__ out,
                 int C, int H, int W, int A, int Otot, int P, int M) {
    extern __shared__ char dsm[];
    const uint32_t sb = smem_u32(dsm);

    const int HW = H * W, KC = C >> 6, nchunks = 9 * KC;
    const int t = threadIdx.x, warp = t >> 5, lane = t & 31;
    const int m0 = blockIdx.y * 128, o0 = blockIdx.x * 128;
    const int MT = BATCH * M, A4 = 4 * A;
    const int mwarp = warp >> 2, nwarp = warp & 3;

    // loader: 2 threads per row; each thread 32B of A row + 32B of B row per plane
    const int r = t >> 1, chalf = t & 1;
    const int ma = m0 + r;
    const bool avalid = (ma < MT);
    const int mm = avalid ? ma : 0;
    const int na = mm / M, pa = mm - na * M;
    const int ah_ = pa / W, aw_ = pa - ah_ * W;
    const size_t a_nbase = (size_t)na * HW * C;
    const int ob = o0 + r;
    const bool bvalid = (ob < Otot);
    const size_t b_obase = (size_t)(bvalid ? ob : 0) * C;
    const size_t OC = (size_t)Otot * C;
    const uint32_t dst_r = (uint32_t)r * ROWB + (uint32_t)chalf * 32;

    int accH[4][4][4], accM[4][4][4];
#pragma unroll
    for (int i = 0; i < 4; i++)
#pragma unroll
        for (int j = 0; j < 4; j++)
#pragma unroll
            for (int k = 0; k < 4; k++) { accH[i][j][k] = 0; accM[i][j][k] = 0; }

    const uint32_t a_lmrow = (uint32_t)(mwarp * 64 + (lane & 15)) * ROWB + ((lane >> 4) * 16);
    const uint32_t b_lmrow = (uint32_t)(nwarp * 32 + (lane & 15)) * ROWB + ((lane >> 4) * 16);

#define LOAD_CHUNK(ch) {                                                            \
    const int s_ = (ch) % 3;                                                        \
    const int tap = (ch) / KC, ck = (ch) - tap * KC;                                \
    const int dy = tap / 3 - 1, dx = tap % 3 - 1;                                   \
    const int hh = ah_ + dy, ww = aw_ + dx;                                         \
    const bool aok = avalid && hh >= 0 && hh < H && ww >= 0 && ww < W;              \
    const size_t asrc = xoff + a_nbase + (size_t)(aok ? (hh * W + ww) : 0) * C      \
                        + (ck << 6) + chalf * 32;                                   \
    const size_t bsrc = woff + (size_t)tap * OC + b_obase + (ck << 6) + chalf * 32; \
    const uint32_t az = aok ? 16u : 0u, bz = bvalid ? 16u : 0u;                     \
    const uint32_t d0 = sb + s_ * STG + dst_r;                                      \
    cp16(d0,              g_qa_hi + asrc,      az);                                 \
    cp16(d0 + 16,         g_qa_hi + asrc + 16, az);                                 \
    cp16(d0 + 10240,      g_qa_lo + asrc,      az);                                 \
    cp16(d0 + 10240 + 16, g_qa_lo + asrc + 16, az);                                 \
    cp16(d0 + 20480,      g_qw_hi + bsrc,      bz);                                 \
    cp16(d0 + 20480 + 16, g_qw_hi + bsrc + 16, bz);                                 \
    cp16(d0 + 30720,      g_qw_lo + bsrc,      bz);                                 \
    cp16(d0 + 30720 + 16, g_qw_lo + bsrc + 16, bz);                                 \
    cp_commit(); }

    LOAD_CHUNK(0)
    if (nchunks > 1) LOAD_CHUNK(1)

    for (int ch = 0; ch < nchunks; ch++) {
        if (ch + 2 < nchunks) { LOAD_CHUNK(ch + 2) cp_wait2(); }
        else if (ch + 1 < nchunks) cp_wait1();
        else cp_wait0();
        __syncthreads();

        const uint32_t base = sb + (ch % 3) * STG;
#pragma unroll
        for (int ks = 0; ks < 2; ks++) {
            const uint32_t ko = ks * 32;
            uint32_t ahf[4][4], alf[4][4], bh0[4], bh1[4], bl0[4], bl1[4];
#pragma unroll
            for (int mt = 0; mt < 4; mt++) {
                ldsm4(ahf[mt], base + a_lmrow + mt * (16 * ROWB) + ko);
                ldsm4(alf[mt], base + 10240 + a_lmrow + mt * (16 * ROWB) + ko);
            }
            ldsm4(bh0, base + 20480 + b_lmrow + ko);
            ldsm4(bh1, base + 20480 + b_lmrow + 16 * ROWB + ko);
            ldsm4(bl0, base + 30720 + b_lmrow + ko);
            ldsm4(bl1, base + 30720 + b_lmrow + 16 * ROWB + ko);
#pragma unroll
            for (int mt = 0; mt < 4; mt++) {
#pragma unroll
                for (int ng = 0; ng < 4; ng++) {
                    const uint32_t* bh = (ng < 2) ? bh0 : bh1;
                    const uint32_t* bl = (ng < 2) ? bl0 : bl1;
                    const int pr = ng & 1;
                    mma_s8(accH[mt][ng], ahf[mt], bh[pr], bh[pr + 2]);
                    mma_s8(accM[mt][ng], ahf[mt], bl[pr], bl[pr + 2]);
                    mma_s8(accM[mt][ng], alf[mt], bh[pr], bh[pr + 2]);
                }
            }
        }
        __syncthreads();
    }

    // ---- epilogue: dequant + bias + scatter ----
    const float sA = __uint_as_float(g_sAbits[lvl]);
    float* bbox = out;
    float* cls  = out + CLS_OFF;
#pragma unroll
    for (int mt = 0; mt < 4; mt++) {
#pragma unroll
        for (int half = 0; half < 2; half++) {
            const int m = m0 + mwarp * 64 + mt * 16 + (lane >> 2) + half * 8;
            if (m >= MT) continue;
            const int n = m / M, p = m - n * M;
            const size_t obase = (size_t)n * NPOS + P + (size_t)p * A;
#pragma unroll
            for (int ng = 0; ng < 4; ng++) {
#pragma unroll
                for (int e = 0; e < 2; e++) {
                    const int o = o0 + nwarp * 32 + ng * 8 + (lane & 3) * 2 + e;
                    if (o >= Otot) continue;
                    const float sc = sA * g_sw[swoff + o] * INV2;
                    float v = (16384.0f * (float)accH[mt][ng][half * 2 + e]
                               + 128.0f * (float)accM[mt][ng][half * 2 + e]) * sc;
                    if (o < A4) {
                        v += regb[o];
                        bbox[(obase + (o >> 2)) * 4 + (o & 3)] = v;
                    } else {
                        const int q = o - A4;
                        v += clsb[q];
                        const int a = q / 91;
                        cls[(obase + a) * 91 + (q - a * 91)] = v;
                    }
                }
            }
        }
    }
}

// ------------------------------- launch ------------------------------------
extern "C" void kernel_launch(void* const* d_in, const int* in_sizes, int n_in,
                              void* d_out, int out_size) {
    static const int    Cs[6]   = {512, 1024, 512, 256, 256, 256};
    static const int    Ss[6]   = {38, 19, 10, 5, 3, 1};
    static const int    Aa[6]   = {4, 6, 6, 6, 4, 4};
    static const int    Ps[6]   = {0, 5776, 7942, 8542, 8692, 8728};
    static const size_t XOFF[6] = {0, 23658496, 35487744, 37126144, 37330944, 37404672};
    static const size_t WOFF[6] = {0, 1751040, 7004160, 9630720, 10944000, 11819520};
    static const size_t SWOFF[6]= {0, 380, 950, 1520, 2090, 2470};
    const int SMEM = 3 * STG;

    cudaFuncSetAttribute(gemm_kernel, cudaFuncAttributeMaxDynamicSharedMemorySize, SMEM);
    float* out = (float*)d_out;

    zero_sa_kernel<<<1, 32>>>();

    for (int i = 0; i < 6; i++) {
        const int C = Cs[i], S = Ss[i], A = Aa[i];
        const int HW = S * S, Otot = 95 * A, A4 = 4 * A;
        const float* feat = (const float*)d_in[5 * i + 0];
        const float* clsw = (const float*)d_in[5 * i + 1];
        const float* regw = (const float*)d_in[5 * i + 3];
        const int total = BATCH * C * HW;
        int nb = (total + 255) / 256; if (nb > 1024) nb = 1024;
        amax_x_kernel<<<nb, 256>>>(feat, total, i);
        dim3 tg((HW + 31) / 32, C / 32, BATCH);
        transpose_q_kernel<<<tg, dim3(32, 8)>>>(feat, XOFF[i], C, HW, i);
        wamax_kernel<<<Otot, 256>>>(regw, clsw, SWOFF[i], C, A4);
        pack_wq_kernel<<<(Otot * C + 255) / 256, 256>>>(regw, clsw, WOFF[i], SWOFF[i], C, A4, Otot);
    }

    for (int i = 0; i < 6; i++) {
        const int C = Cs[i], S = Ss[i], A = Aa[i];
        const int Otot = 95 * A, M = S * S, MT = BATCH * M;
        const float* clsb = (const float*)d_in[5 * i + 2];
        const float* regb = (const float*)d_in[5 * i + 4];
        dim3 grid((Otot + 127) / 128, (MT + 127) / 128);
        gemm_kernel<<<grid, 256, SMEM>>>(XOFF[i], WOFF[i], SWOFF[i], i, regb, clsb, out,
                                         C, S, S, A, Otot, Ps[i], M);
    }
}

// round 7
// speedup vs baseline: 3.2898x; 3.2898x over previous
#include <cuda_runtime.h>
#include <cuda_fp16.h>
#include <stdint.h>

#define BATCH 32
#define NPOS  8732
#define CLS_OFF ((size_t)BATCH * NPOS * 4)

// static scratch: activations split into 2 fp16 planes, weights 1 plane
__device__ __half g_xt_hi[37412864];
__device__ __half g_xt_lo[37412864];
__device__ __half g_wt[12695040];

__device__ __forceinline__ uint32_t smem_u32(const void* p) {
    uint32_t r;
    asm("{ .reg .u64 t; cvta.to.shared.u64 t, %1; cvt.u32.u64 %0, t; }" : "=r"(r) : "l"(p));
    return r;
}
__device__ __forceinline__ void cp16(uint32_t dst, const void* src, uint32_t sz) {
    asm volatile("cp.async.cg.shared.global [%0], [%1], 16, %2;"
                 :: "r"(dst), "l"(src), "r"(sz) : "memory");
}
__device__ __forceinline__ void cp_commit() { asm volatile("cp.async.commit_group;" ::: "memory"); }
__device__ __forceinline__ void cp_wait1()  { asm volatile("cp.async.wait_group 1;" ::: "memory"); }
__device__ __forceinline__ void cp_wait0()  { asm volatile("cp.async.wait_group 0;" ::: "memory"); }
__device__ __forceinline__ void ldsm4(uint32_t* r, uint32_t a) {
    asm volatile("ldmatrix.sync.aligned.m8n8.x4.shared.b16 {%0,%1,%2,%3}, [%4];"
                 : "=r"(r[0]), "=r"(r[1]), "=r"(r[2]), "=r"(r[3]) : "r"(a));
}
__device__ __forceinline__ void mma_f16(float* d, const uint32_t* a, uint32_t b0, uint32_t b1) {
    asm volatile("mma.sync.aligned.m16n8k16.row.col.f32.f16.f16.f32 "
                 "{%0,%1,%2,%3}, {%4,%5,%6,%7}, {%8,%9}, {%0,%1,%2,%3};"
                 : "+f"(d[0]), "+f"(d[1]), "+f"(d[2]), "+f"(d[3])
                 : "r"(a[0]), "r"(a[1]), "r"(a[2]), "r"(a[3]), "r"(b0), "r"(b1));
}

__global__ void noop_kernel() {}

// ---- prep 1: activation transpose [n][c][p] -> [n][p][c], fp16 hi/lo ----
__global__ void transpose_kernel(const float* __restrict__ x, size_t xoff, int C, int HW) {
    __shared__ float tile[32][33];
    const int n = blockIdx.z, p0 = blockIdx.x * 32, c0 = blockIdx.y * 32;
    const int tx = threadIdx.x, ty = threadIdx.y;
    const float* xb = x + (size_t)n * C * HW;
#pragma unroll
    for (int k = 0; k < 4; k++) {
        int c = c0 + ty + 8 * k, p = p0 + tx;
        tile[ty + 8 * k][tx] = (p < HW) ? xb[(size_t)c * HW + p] : 0.f;
    }
    __syncthreads();
#pragma unroll
    for (int k = 0; k < 4; k++) {
        int p = p0 + ty + 8 * k, c = c0 + tx;
        if (p < HW) {
            float v = tile[tx][ty + 8 * k];
            __half hi = __float2half_rn(v);
            __half lo = __float2half_rn(v - __half2float(hi));
            size_t o = xoff + ((size_t)n * HW + p) * C + c;
            g_xt_hi[o] = hi; g_xt_lo[o] = lo;
        }
    }
}

// ---- prep 2: weights -> [tap][o][c] fp16 (o = reg then cls) ----
__global__ void pack_w_kernel(const float* __restrict__ regw, const float* __restrict__ clsw,
                              size_t woff, int C, int A4, int Otot) {
    int idx = blockIdx.x * blockDim.x + threadIdx.x;
    if (idx >= Otot * C) return;
    int c = idx % C, o = idx / C;
    const float* src = (o < A4) ? (regw + ((size_t)o * C + c) * 9)
                                : (clsw + ((size_t)(o - A4) * C + c) * 9);
#pragma unroll
    for (int tap = 0; tap < 9; tap++)
        g_wt[woff + ((size_t)tap * Otot + o) * C + c] = __float2half_rn(src[tap]);
}

// ---- main GEMM: fp16 2-term mma.m16n8k16, CTA 128x128, k-chunk 64 ----
// 8 warps (2x4), warp tile 64x32. smem/stage: Ahi|Alo|B @ 18432B (144B rows).
#define ROWB 144
#define PLA  18432
#define STG  55296

__global__ __launch_bounds__(256, 2)
void gemm_kernel(size_t xoff, size_t woff,
                 const float* __restrict__ regb, const float* __restrict__ clsb,
                 float* __restrict__ out,
                 int C, int H, int W, int A, int Otot, int P, int M) {
    extern __shared__ char dsm[];
    const uint32_t sb = smem_u32(dsm);

    const int HW = H * W, KC = C >> 6, nchunks = 9 * KC;
    const int t = threadIdx.x, warp = t >> 5, lane = t & 31;
    const int m0 = blockIdx.y * 128, o0 = blockIdx.x * 128;
    const int MT = BATCH * M, A4 = 4 * A;
    const int mwarp = warp >> 2, nwarp = warp & 3;

    // loader: 2 threads per row, 64B (32 halves) each
    const int r = t >> 1, chalf = t & 1;
    const int ma = m0 + r;
    const bool avalid = (ma < MT);
    const int mm = avalid ? ma : 0;
    const int na = mm / M, pa = mm - na * M;
    const int ah_ = pa / W, aw_ = pa - ah_ * W;
    const size_t a_nbase = (size_t)na * HW * C;
    const int ob = o0 + r;
    const bool bvalid = (ob < Otot);
    const size_t b_obase = (size_t)(bvalid ? ob : 0) * C;
    const size_t OC = (size_t)Otot * C;
    const uint32_t dst_r = (uint32_t)r * ROWB + (uint32_t)chalf * 64;

    float acc[4][4][4];
#pragma unroll
    for (int i = 0; i < 4; i++)
#pragma unroll
        for (int j = 0; j < 4; j++)
#pragma unroll
            for (int k = 0; k < 4; k++) acc[i][j][k] = 0.f;

    const uint32_t a_lmrow = (uint32_t)(mwarp * 64 + (lane & 15)) * ROWB + ((lane >> 4) * 16);
    const int nl = (lane & 7) + ((lane >> 4) << 3);
    const uint32_t b_lmrow = (uint32_t)(nwarp * 32 + nl) * ROWB + (((lane >> 3) & 1) * 16);

#define LOAD_CHUNK(ch, s_) {                                                        \
    const int tap = (ch) / KC, ck = (ch) - tap * KC;                                \
    const int dy = tap / 3 - 1, dx = tap % 3 - 1;                                   \
    const int hh = ah_ + dy, ww = aw_ + dx;                                         \
    const bool aok = avalid && hh >= 0 && hh < H && ww >= 0 && ww < W;              \
    const size_t asrc = xoff + a_nbase + (size_t)(aok ? (hh * W + ww) : 0) * C      \
                        + (ck << 6) + chalf * 32;                                   \
    const size_t bsrc = woff + (size_t)tap * OC + b_obase + (ck << 6) + chalf * 32; \
    const uint32_t az = aok ? 16u : 0u, bz = bvalid ? 16u : 0u;                     \
    const uint32_t d0 = sb + (s_) * STG + dst_r;                                    \
    _Pragma("unroll")                                                               \
    for (int c = 0; c < 4; c++) {                                                   \
        cp16(d0 + c * 16,           g_xt_hi + asrc + c * 8, az);                    \
        cp16(d0 + PLA + c * 16,     g_xt_lo + asrc + c * 8, az);                    \
        cp16(d0 + 2 * PLA + c * 16, g_wt    + bsrc + c * 8, bz);                    \
    }                                                                               \
    cp_commit(); }

    LOAD_CHUNK(0, 0)

    for (int ch = 0; ch < nchunks; ch++) {
        const int s = ch & 1;
        if (ch + 1 < nchunks) { LOAD_CHUNK(ch + 1, s ^ 1) cp_wait1(); }
        else cp_wait0();
        __syncthreads();

        const uint32_t base = sb + s * STG;
#pragma unroll
        for (int ks = 0; ks < 4; ks++) {
            const uint32_t ko = ks * 32;
            uint32_t ah[4][4], al[4][4], bf[2][4];
#pragma unroll
            for (int mt = 0; mt < 4; mt++) {
                ldsm4(ah[mt], base + a_lmrow + mt * (16 * ROWB) + ko);
                ldsm4(al[mt], base + PLA + a_lmrow + mt * (16 * ROWB) + ko);
            }
#pragma unroll
            for (int bp = 0; bp < 2; bp++)
                ldsm4(bf[bp], base + 2 * PLA + b_lmrow + bp * (16 * ROWB) + ko);
            // term 1: ah*b (all 16 accs), then term 2: al*b — long RAW distance
#pragma unroll
            for (int mt = 0; mt < 4; mt++)
#pragma unroll
                for (int nt = 0; nt < 4; nt++) {
                    const int bp = nt >> 1, su = (nt & 1) * 2;
                    mma_f16(acc[mt][nt], ah[mt], bf[bp][su], bf[bp][su + 1]);
                }
#pragma unroll
            for (int mt = 0; mt < 4; mt++)
#pragma unroll
                for (int nt = 0; nt < 4; nt++) {
                    const int bp = nt >> 1, su = (nt & 1) * 2;
                    mma_f16(acc[mt][nt], al[mt], bf[bp][su], bf[bp][su + 1]);
                }
        }
        __syncthreads();
    }

    // ---- epilogue: bias + scatter ----
    float* bbox = out;
    float* cls  = out + CLS_OFF;
#pragma unroll
    for (int mt = 0; mt < 4; mt++) {
#pragma unroll
        for (int half = 0; half < 2; half++) {
            const int m = m0 + mwarp * 64 + mt * 16 + (lane >> 2) + half * 8;
            if (m >= MT) continue;
            const int n = m / M, p = m - n * M;
            const size_t obase = (size_t)n * NPOS + P + (size_t)p * A;
#pragma unroll
            for (int nt = 0; nt < 4; nt++) {
#pragma unroll
                for (int e = 0; e < 2; e++) {
                    const int o = o0 + nwarp * 32 + nt * 8 + (lane & 3) * 2 + e;
                    if (o >= Otot) continue;
                    float v = acc[mt][nt][half * 2 + e];
                    if (o < A4) {
                        v += regb[o];
                        bbox[(obase + (o >> 2)) * 4 + (o & 3)] = v;
                    } else {
                        const int q = o - A4;
                        v += clsb[q];
                        const int a = q / 91;
                        cls[(obase + a) * 91 + (q - a * 91)] = v;
                    }
                }
            }
        }
    }
}

// ------------------------------- launch ------------------------------------
extern "C" void kernel_launch(void* const* d_in, const int* in_sizes, int n_in,
                              void* d_out, int out_size) {
    static const int    Cs[6]   = {512, 1024, 512, 256, 256, 256};
    static const int    Ss[6]   = {38, 19, 10, 5, 3, 1};
    static const int    Aa[6]   = {4, 6, 6, 6, 4, 4};
    static const int    Ps[6]   = {0, 5776, 7942, 8542, 8692, 8728};
    static const size_t XOFF[6] = {0, 23658496, 35487744, 37126144, 37330944, 37404672};
    static const size_t WOFF[6] = {0, 1751040, 7004160, 9630720, 10944000, 11819520};
    const int SMEM = 2 * STG;   // 110592

    cudaFuncSetAttribute(gemm_kernel, cudaFuncAttributeMaxDynamicSharedMemorySize, SMEM);
    float* out = (float*)d_out;

    auto prep = [&](int i) {
        const int C = Cs[i], S = Ss[i], A = Aa[i];
        const int HW = S * S, Otot = 95 * A, A4 = 4 * A;
        const float* feat = (const float*)d_in[5 * i + 0];
        const float* clsw = (const float*)d_in[5 * i + 1];
        const float* regw = (const float*)d_in[5 * i + 3];
        dim3 tg((HW + 31) / 32, C / 32, BATCH);
        transpose_kernel<<<tg, dim3(32, 8)>>>(feat, XOFF[i], C, HW);
        pack_w_kernel<<<(Otot * C + 255) / 256, 256>>>(regw, clsw, WOFF[i], C, A4, Otot);
    };
    auto gemm = [&](int i) {
        const int C = Cs[i], S = Ss[i], A = Aa[i];
        const int Otot = 95 * A, M = S * S, MT = BATCH * M;
        const float* clsb = (const float*)d_in[5 * i + 2];
        const float* regb = (const float*)d_in[5 * i + 4];
        dim3 grid((Otot + 127) / 128, (MT + 127) / 128);
        gemm_kernel<<<grid, 256, SMEM>>>(XOFF[i], WOFF[i], regb, clsb, out,
                                         C, S, S, A, Otot, Ps[i], M);
    };

    // ncu profiles the 4th launch -> make it GEMM level 0
    prep(0);                    // 1, 2
    noop_kernel<<<1, 32>>>();   // 3
    gemm(0);                    // 4  <-- profiled
    for (int i = 1; i < 6; i++) prep(i);
    for (int i = 1; i < 6; i++) gemm(i);
}

// round 8
// speedup vs baseline: 4.9225x; 1.4963x over previous
#include <cuda_runtime.h>
#include <cuda_fp16.h>
#include <stdint.h>

#define BATCH 32
#define NPOS  8732
#define CLS_OFF ((size_t)BATCH * NPOS * 4)

// static scratch: fp16 activations (transposed) and packed fp16 weights
__device__ __half g_xt[37412864];
__device__ __half g_wt[12695040];

__device__ __forceinline__ uint32_t smem_u32(const void* p) {
    uint32_t r;
    asm("{ .reg .u64 t; cvta.to.shared.u64 t, %1; cvt.u32.u64 %0, t; }" : "=r"(r) : "l"(p));
    return r;
}
__device__ __forceinline__ void cp16(uint32_t dst, const void* src, uint32_t sz) {
    asm volatile("cp.async.cg.shared.global [%0], [%1], 16, %2;"
                 :: "r"(dst), "l"(src), "r"(sz) : "memory");
}
__device__ __forceinline__ void cp_commit() { asm volatile("cp.async.commit_group;" ::: "memory"); }
__device__ __forceinline__ void cp_wait2()  { asm volatile("cp.async.wait_group 2;" ::: "memory"); }
__device__ __forceinline__ void cp_wait1()  { asm volatile("cp.async.wait_group 1;" ::: "memory"); }
__device__ __forceinline__ void cp_wait0()  { asm volatile("cp.async.wait_group 0;" ::: "memory"); }
__device__ __forceinline__ void ldsm4(uint32_t* r, uint32_t a) {
    asm volatile("ldmatrix.sync.aligned.m8n8.x4.shared.b16 {%0,%1,%2,%3}, [%4];"
                 : "=r"(r[0]), "=r"(r[1]), "=r"(r[2]), "=r"(r[3]) : "r"(a));
}
__device__ __forceinline__ void mma_f16(float* d, const uint32_t* a, uint32_t b0, uint32_t b1) {
    asm volatile("mma.sync.aligned.m16n8k16.row.col.f32.f16.f16.f32 "
                 "{%0,%1,%2,%3}, {%4,%5,%6,%7}, {%8,%9}, {%0,%1,%2,%3};"
                 : "+f"(d[0]), "+f"(d[1]), "+f"(d[2]), "+f"(d[3])
                 : "r"(a[0]), "r"(a[1]), "r"(a[2]), "r"(a[3]), "r"(b0), "r"(b1));
}

__global__ void noop_kernel() {}

// ---- prep 1: activation transpose [n][c][p] -> [n][p][c], fp16 ----
__global__ void transpose_kernel(const float* __restrict__ x, size_t xoff, int C, int HW) {
    __shared__ float tile[32][33];
    const int n = blockIdx.z, p0 = blockIdx.x * 32, c0 = blockIdx.y * 32;
    const int tx = threadIdx.x, ty = threadIdx.y;
    const float* xb = x + (size_t)n * C * HW;
#pragma unroll
    for (int k = 0; k < 4; k++) {
        int c = c0 + ty + 8 * k, p = p0 + tx;
        tile[ty + 8 * k][tx] = (p < HW) ? xb[(size_t)c * HW + p] : 0.f;
    }
    __syncthreads();
#pragma unroll
    for (int k = 0; k < 4; k++) {
        int p = p0 + ty + 8 * k, c = c0 + tx;
        if (p < HW)
            g_xt[xoff + ((size_t)n * HW + p) * C + c] = __float2half_rn(tile[tx][ty + 8 * k]);
    }
}

// ---- prep 2: weights -> [tap][o][c] fp16 (o = reg then cls) ----
__global__ void pack_w_kernel(const float* __restrict__ regw, const float* __restrict__ clsw,
                              size_t woff, int C, int A4, int Otot) {
    int idx = blockIdx.x * blockDim.x + threadIdx.x;
    if (idx >= Otot * C) return;
    int c = idx % C, o = idx / C;
    const float* src = (o < A4) ? (regw + ((size_t)o * C + c) * 9)
                                : (clsw + ((size_t)(o - A4) * C + c) * 9);
#pragma unroll
    for (int tap = 0; tap < 9; tap++)
        g_wt[woff + ((size_t)tap * Otot + o) * C + c] = __float2half_rn(src[tap]);
}

// ---- main GEMM: fp16 single-term m16n8k16, CTA 128x128, k-chunk 64 ----
// 8 warps (2x4), warp tile 64x32. stage: A|B @ 18432B each (144B rows), 3 stages.
#define ROWB 144
#define PLA  18432
#define STG  36864

__global__ __launch_bounds__(256, 2)
void gemm_kernel(size_t xoff, size_t woff,
                 const float* __restrict__ regb, const float* __restrict__ clsb,
                 float* __restrict__ out,
                 int C, int H, int W, int A, int Otot, int P, int M) {
    extern __shared__ char dsm[];
    const uint32_t sb = smem_u32(dsm);

    const int HW = H * W, KC = C >> 6, nchunks = 9 * KC;
    const int t = threadIdx.x, warp = t >> 5, lane = t & 31;
    const int m0 = blockIdx.y * 128, o0 = blockIdx.x * 128;
    const int MT = BATCH * M, A4 = 4 * A;
    const int mwarp = warp >> 2, nwarp = warp & 3;

    // loader: 2 threads per row, 64B (32 halves) each
    const int r = t >> 1, chalf = t & 1;
    const int ma = m0 + r;
    const bool avalid = (ma < MT);
    const int mm = avalid ? ma : 0;
    const int na = mm / M, pa = mm - na * M;
    const int ah_ = pa / W, aw_ = pa - ah_ * W;
    const size_t a_nbase = (size_t)na * HW * C;
    const int ob = o0 + r;
    const bool bvalid = (ob < Otot);
    const size_t b_obase = (size_t)(bvalid ? ob : 0) * C;
    const size_t OC = (size_t)Otot * C;
    const uint32_t dst_r = (uint32_t)r * ROWB + (uint32_t)chalf * 64;

    float acc[4][4][4];
#pragma unroll
    for (int i = 0; i < 4; i++)
#pragma unroll
        for (int j = 0; j < 4; j++)
#pragma unroll
            for (int k = 0; k < 4; k++) acc[i][j][k] = 0.f;

    const uint32_t a_lmrow = (uint32_t)(mwarp * 64 + (lane & 15)) * ROWB + ((lane >> 4) * 16);
    const int nl = (lane & 7) + ((lane >> 4) << 3);
    const uint32_t b_lmrow = (uint32_t)(nwarp * 32 + nl) * ROWB + (((lane >> 3) & 1) * 16);

#define LOAD_CHUNK(ch) {                                                            \
    const int s_ = (ch) % 3;                                                        \
    const int tap = (ch) / KC, ck = (ch) - tap * KC;                                \
    const int dy = tap / 3 - 1, dx = tap % 3 - 1;                                   \
    const int hh = ah_ + dy, ww = aw_ + dx;                                         \
    const bool aok = avalid && hh >= 0 && hh < H && ww >= 0 && ww < W;              \
    const size_t asrc = xoff + a_nbase + (size_t)(aok ? (hh * W + ww) : 0) * C      \
                        + (ck << 6) + chalf * 32;                                   \
    const size_t bsrc = woff + (size_t)tap * OC + b_obase + (ck << 6) + chalf * 32; \
    const uint32_t az = aok ? 16u : 0u, bz = bvalid ? 16u : 0u;                     \
    const uint32_t d0 = sb + s_ * STG + dst_r;                                      \
    _Pragma("unroll")                                                               \
    for (int c = 0; c < 4; c++) {                                                   \
        cp16(d0 + c * 16,       g_xt + asrc + c * 8, az);                           \
        cp16(d0 + PLA + c * 16, g_wt + bsrc + c * 8, bz);                           \
    }                                                                               \
    cp_commit(); }

    LOAD_CHUNK(0)
    if (nchunks > 1) LOAD_CHUNK(1)

    for (int ch = 0; ch < nchunks; ch++) {
        if (ch + 2 < nchunks) { LOAD_CHUNK(ch + 2) cp_wait2(); }
        else if (ch + 1 < nchunks) cp_wait1();
        else cp_wait0();
        __syncthreads();

        const uint32_t base = sb + (ch % 3) * STG;
#pragma unroll
        for (int ks = 0; ks < 4; ks++) {
            const uint32_t ko = ks * 32;
            uint32_t ah[4][4], bf[2][4];
#pragma unroll
            for (int mt = 0; mt < 4; mt++)
                ldsm4(ah[mt], base + a_lmrow + mt * (16 * ROWB) + ko);
#pragma unroll
            for (int bp = 0; bp < 2; bp++)
                ldsm4(bf[bp], base + PLA + b_lmrow + bp * (16 * ROWB) + ko);
#pragma unroll
            for (int mt = 0; mt < 4; mt++)
#pragma unroll
                for (int nt = 0; nt < 4; nt++) {
                    const int bp = nt >> 1, su = (nt & 1) * 2;
                    mma_f16(acc[mt][nt], ah[mt], bf[bp][su], bf[bp][su + 1]);
                }
        }
        __syncthreads();
    }

    // ---- epilogue: bias + scatter ----
    float* bbox = out;
    float* cls  = out + CLS_OFF;
#pragma unroll
    for (int mt = 0; mt < 4; mt++) {
#pragma unroll
        for (int half = 0; half < 2; half++) {
            const int m = m0 + mwarp * 64 + mt * 16 + (lane >> 2) + half * 8;
            if (m >= MT) continue;
            const int n = m / M, p = m - n * M;
            const size_t obase = (size_t)n * NPOS + P + (size_t)p * A;
#pragma unroll
            for (int nt = 0; nt < 4; nt++) {
#pragma unroll
                for (int e = 0; e < 2; e++) {
                    const int o = o0 + nwarp * 32 + nt * 8 + (lane & 3) * 2 + e;
                    if (o >= Otot) continue;
                    float v = acc[mt][nt][half * 2 + e];
                    if (o < A4) {
                        v += regb[o];
                        bbox[(obase + (o >> 2)) * 4 + (o & 3)] = v;
                    } else {
                        const int q = o - A4;
                        v += clsb[q];
                        const int a = q / 91;
                        cls[(obase + a) * 91 + (q - a * 91)] = v;
                    }
                }
            }
        }
    }
}

// ------------------------------- launch ------------------------------------
extern "C" void kernel_launch(void* const* d_in, const int* in_sizes, int n_in,
                              void* d_out, int out_size) {
    static const int    Cs[6]   = {512, 1024, 512, 256, 256, 256};
    static const int    Ss[6]   = {38, 19, 10, 5, 3, 1};
    static const int    Aa[6]   = {4, 6, 6, 6, 4, 4};
    static const int    Ps[6]   = {0, 5776, 7942, 8542, 8692, 8728};
    static const size_t XOFF[6] = {0, 23658496, 35487744, 37126144, 37330944, 37404672};
    static const size_t WOFF[6] = {0, 1751040, 7004160, 9630720, 10944000, 11819520};
    const int SMEM = 3 * STG;   // 110592

    cudaFuncSetAttribute(gemm_kernel, cudaFuncAttributeMaxDynamicSharedMemorySize, SMEM);
    float* out = (float*)d_out;

    auto prep = [&](int i) {
        const int C = Cs[i], S = Ss[i], A = Aa[i];
        const int HW = S * S, Otot = 95 * A, A4 = 4 * A;
        const float* feat = (const float*)d_in[5 * i + 0];
        const float* clsw = (const float*)d_in[5 * i + 1];
        const float* regw = (const float*)d_in[5 * i + 3];
        dim3 tg((HW + 31) / 32, C / 32, BATCH);
        transpose_kernel<<<tg, dim3(32, 8)>>>(feat, XOFF[i], C, HW);
        pack_w_kernel<<<(Otot * C + 255) / 256, 256>>>(regw, clsw, WOFF[i], C, A4, Otot);
    };
    auto gemm = [&](int i) {
        const int C = Cs[i], S = Ss[i], A = Aa[i];
        const int Otot = 95 * A, M = S * S, MT = BATCH * M;
        const float* clsb = (const float*)d_in[5 * i + 2];
        const float* regb = (const float*)d_in[5 * i + 4];
        dim3 grid((Otot + 127) / 128, (MT + 127) / 128);
        gemm_kernel<<<grid, 256, SMEM>>>(XOFF[i], WOFF[i], regb, clsb, out,
                                         C, S, S, A, Otot, Ps[i], M);
    };

    // ncu profiles the 4th launch -> make it GEMM level 0
    prep(0);                    // 1, 2
    noop_kernel<<<1, 32>>>();   // 3
    gemm(0);                    // 4  <-- profiled
    for (int i = 1; i < 6; i++) prep(i);
    for (int i = 1; i < 6; i++) gemm(i);
}

// round 9
// speedup vs baseline: 5.1259x; 1.0413x over previous
#include <cuda_runtime.h>
#include <cuda_fp16.h>
#include <stdint.h>

#define BATCH 32
#define NPOS  8732
#define CLS_OFF ((size_t)BATCH * NPOS * 4)

// static scratch: fp16 activations (transposed) and packed fp16 weights
__device__ __half g_xt[37412864];
__device__ __half g_wt[12695040];

__device__ __forceinline__ uint32_t smem_u32(const void* p) {
    uint32_t r;
    asm("{ .reg .u64 t; cvta.to.shared.u64 t, %1; cvt.u32.u64 %0, t; }" : "=r"(r) : "l"(p));
    return r;
}
__device__ __forceinline__ void cp16(uint32_t dst, const void* src, uint32_t sz) {
    asm volatile("cp.async.cg.shared.global [%0], [%1], 16, %2;"
                 :: "r"(dst), "l"(src), "r"(sz) : "memory");
}
__device__ __forceinline__ void cp_commit() { asm volatile("cp.async.commit_group;" ::: "memory"); }
__device__ __forceinline__ void cp_wait1()  { asm volatile("cp.async.wait_group 1;" ::: "memory"); }
__device__ __forceinline__ void ldsm4(uint32_t* r, uint32_t a) {
    asm volatile("ldmatrix.sync.aligned.m8n8.x4.shared.b16 {%0,%1,%2,%3}, [%4];"
                 : "=r"(r[0]), "=r"(r[1]), "=r"(r[2]), "=r"(r[3]) : "r"(a));
}
__device__ __forceinline__ void mma_f16(float* d, const uint32_t* a, uint32_t b0, uint32_t b1) {
    asm volatile("mma.sync.aligned.m16n8k16.row.col.f32.f16.f16.f32 "
                 "{%0,%1,%2,%3}, {%4,%5,%6,%7}, {%8,%9}, {%0,%1,%2,%3};"
                 : "+f"(d[0]), "+f"(d[1]), "+f"(d[2]), "+f"(d[3])
                 : "r"(a[0]), "r"(a[1]), "r"(a[2]), "r"(a[3]), "r"(b0), "r"(b1));
}

__global__ void noop_kernel() {}

// ---- prep 1: activation transpose [n][c][p] -> [n][p][c], fp16 ----
__global__ void transpose_kernel(const float* __restrict__ x, size_t xoff, int C, int HW) {
    __shared__ float tile[32][33];
    const int n = blockIdx.z, p0 = blockIdx.x * 32, c0 = blockIdx.y * 32;
    const int tx = threadIdx.x, ty = threadIdx.y;
    const float* xb = x + (size_t)n * C * HW;
#pragma unroll
    for (int k = 0; k < 4; k++) {
        int c = c0 + ty + 8 * k, p = p0 + tx;
        tile[ty + 8 * k][tx] = (p < HW) ? xb[(size_t)c * HW + p] : 0.f;
    }
    __syncthreads();
#pragma unroll
    for (int k = 0; k < 4; k++) {
        int p = p0 + ty + 8 * k, c = c0 + tx;
        if (p < HW)
            g_xt[xoff + ((size_t)n * HW + p) * C + c] = __float2half_rn(tile[tx][ty + 8 * k]);
    }
}

// ---- prep 2: weights -> [tap][o][c] fp16 (o = reg then cls) ----
__global__ void pack_w_kernel(const float* __restrict__ regw, const float* __restrict__ clsw,
                              size_t woff, int C, int A4, int Otot) {
    int idx = blockIdx.x * blockDim.x + threadIdx.x;
    if (idx >= Otot * C) return;
    int c = idx % C, o = idx / C;
    const float* src = (o < A4) ? (regw + ((size_t)o * C + c) * 9)
                                : (clsw + ((size_t)(o - A4) * C + c) * 9);
#pragma unroll
    for (int tap = 0; tap < 9; tap++)
        g_wt[woff + ((size_t)tap * Otot + o) * C + c] = __float2half_rn(src[tap]);
}

// ---- main GEMM: fp16 m16n8k16, CTA 128x128, k-chunk 64, 3-stage ----
// 8 warps (2x4), warp tile 64x32; warp-staggered ks order; 1 sync/chunk.
#define ROWB 144
#define PLA  18432
#define STG  36864

__global__ __launch_bounds__(256, 2)
void gemm_kernel(size_t xoff, size_t woff,
                 const float* __restrict__ regb, const float* __restrict__ clsb,
                 float* __restrict__ out,
                 int C, int H, int W, int A, int Otot, int P, int M) {
    extern __shared__ char dsm[];
    const uint32_t sb = smem_u32(dsm);

    const int HW = H * W, KC = C >> 6, nchunks = 9 * KC;
    const int t = threadIdx.x, warp = t >> 5, lane = t & 31;
    const int m0 = blockIdx.y * 128, o0 = blockIdx.x * 128;
    const int MT = BATCH * M, A4 = 4 * A;
    const int mwarp = warp >> 2, nwarp = warp & 3;
    const int kofs = warp & 3;              // ks-stagger per warp

    // loader: 2 threads per row, 64B (32 halves) each
    const int r = t >> 1, chalf = t & 1;
    const int ma = m0 + r;
    const bool avalid = (ma < MT);
    const int mm = avalid ? ma : 0;
    const int na = mm / M, pa = mm - na * M;
    const int ah_ = pa / W, aw_ = pa - ah_ * W;
    const size_t a_nbase = (size_t)na * HW * C;
    const int ob = o0 + r;
    const bool bvalid = (ob < Otot);
    const size_t b_obase = (size_t)(bvalid ? ob : 0) * C;
    const size_t OC = (size_t)Otot * C;
    const uint32_t dst_r = (uint32_t)r * ROWB + (uint32_t)chalf * 64;

    float acc[4][4][4];
#pragma unroll
    for (int i = 0; i < 4; i++)
#pragma unroll
        for (int j = 0; j < 4; j++)
#pragma unroll
            for (int k = 0; k < 4; k++) acc[i][j][k] = 0.f;

    const uint32_t a_lmrow = (uint32_t)(mwarp * 64 + (lane & 15)) * ROWB + ((lane >> 4) * 16);
    const int nl = (lane & 7) + ((lane >> 4) << 3);
    const uint32_t b_lmrow = (uint32_t)(nwarp * 32 + nl) * ROWB + (((lane >> 3) & 1) * 16);

#define LOAD_CHUNK(ch) {                                                            \
    const int s_ = (ch) % 3;                                                        \
    const int tap = (ch) / KC, ck = (ch) - tap * KC;                                \
    const int dy = tap / 3 - 1, dx = tap % 3 - 1;                                   \
    const int hh = ah_ + dy, ww = aw_ + dx;                                         \
    const bool aok = avalid && hh >= 0 && hh < H && ww >= 0 && ww < W;              \
    const size_t asrc = xoff + a_nbase + (size_t)(aok ? (hh * W + ww) : 0) * C      \
                        + (ck << 6) + chalf * 32;                                   \
    const size_t bsrc = woff + (size_t)tap * OC + b_obase + (ck << 6) + chalf * 32; \
    const uint32_t az = aok ? 16u : 0u, bz = bvalid ? 16u : 0u;                     \
    const uint32_t d0 = sb + s_ * STG + dst_r;                                      \
    _Pragma("unroll")                                                               \
    for (int c = 0; c < 4; c++) {                                                   \
        cp16(d0 + c * 16,       g_xt + asrc + c * 8, az);                           \
        cp16(d0 + PLA + c * 16, g_wt + bsrc + c * 8, bz);                           \
    }                                                                               \
    cp_commit(); }

    LOAD_CHUNK(0)
    LOAD_CHUNK(1)

    for (int ch = 0; ch < nchunks; ch++) {
        cp_wait1();                 // group ch complete (ch+1 may remain in flight)
        __syncthreads();            // data visible; stage (ch+2)%3 free of readers
        if (ch + 2 < nchunks) { LOAD_CHUNK(ch + 2) }
        else cp_commit();           // empty group keeps wait arithmetic uniform

        const uint32_t base = sb + (ch % 3) * STG;
#pragma unroll
        for (int ks4 = 0; ks4 < 4; ks4++) {
            const uint32_t ko = (uint32_t)((ks4 + kofs) & 3) * 32;
            uint32_t ah[4][4], bf[2][4];
#pragma unroll
            for (int mt = 0; mt < 4; mt++)
                ldsm4(ah[mt], base + a_lmrow + mt * (16 * ROWB) + ko);
#pragma unroll
            for (int bp = 0; bp < 2; bp++)
                ldsm4(bf[bp], base + PLA + b_lmrow + bp * (16 * ROWB) + ko);
#pragma unroll
            for (int mt = 0; mt < 4; mt++)
#pragma unroll
                for (int nt = 0; nt < 4; nt++) {
                    const int bp = nt >> 1, su = (nt & 1) * 2;
                    mma_f16(acc[mt][nt], ah[mt], bf[bp][su], bf[bp][su + 1]);
                }
        }
    }

    // ---- epilogue: bias + scatter ----
    float* bbox = out;
    float* cls  = out + CLS_OFF;
#pragma unroll
    for (int mt = 0; mt < 4; mt++) {
#pragma unroll
        for (int half = 0; half < 2; half++) {
            const int m = m0 + mwarp * 64 + mt * 16 + (lane >> 2) + half * 8;
            if (m >= MT) continue;
            const int n = m / M, p = m - n * M;
            const size_t obase = (size_t)n * NPOS + P + (size_t)p * A;
#pragma unroll
            for (int nt = 0; nt < 4; nt++) {
#pragma unroll
                for (int e = 0; e < 2; e++) {
                    const int o = o0 + nwarp * 32 + nt * 8 + (lane & 3) * 2 + e;
                    if (o >= Otot) continue;
                    float v = acc[mt][nt][half * 2 + e];
                    if (o < A4) {
                        v += regb[o];
                        bbox[(obase + (o >> 2)) * 4 + (o & 3)] = v;
                    } else {
                        const int q = o - A4;
                        v += clsb[q];
                        const int a = q / 91;
                        cls[(obase + a) * 91 + (q - a * 91)] = v;
                    }
                }
            }
        }
    }
}

// ------------------------------- launch ------------------------------------
extern "C" void kernel_launch(void* const* d_in, const int* in_sizes, int n_in,
                              void* d_out, int out_size) {
    static const int    Cs[6]   = {512, 1024, 512, 256, 256, 256};
    static const int    Ss[6]   = {38, 19, 10, 5, 3, 1};
    static const int    Aa[6]   = {4, 6, 6, 6, 4, 4};
    static const int    Ps[6]   = {0, 5776, 7942, 8542, 8692, 8728};
    static const size_t XOFF[6] = {0, 23658496, 35487744, 37126144, 37330944, 37404672};
    static const size_t WOFF[6] = {0, 1751040, 7004160, 9630720, 10944000, 11819520};
    const int SMEM = 3 * STG;   // 110592

    cudaFuncSetAttribute(gemm_kernel, cudaFuncAttributeMaxDynamicSharedMemorySize, SMEM);
    float* out = (float*)d_out;

    auto prep = [&](int i) {
        const int C = Cs[i], S = Ss[i], A = Aa[i];
        const int HW = S * S, Otot = 95 * A, A4 = 4 * A;
        const float* feat = (const float*)d_in[5 * i + 0];
        const float* clsw = (const float*)d_in[5 * i + 1];
        const float* regw = (const float*)d_in[5 * i + 3];
        dim3 tg((HW + 31) / 32, C / 32, BATCH);
        transpose_kernel<<<tg, dim3(32, 8)>>>(feat, XOFF[i], C, HW);
        pack_w_kernel<<<(Otot * C + 255) / 256, 256>>>(regw, clsw, WOFF[i], C, A4, Otot);
    };
    auto gemm = [&](int i) {
        const int C = Cs[i], S = Ss[i], A = Aa[i];
        const int Otot = 95 * A, M = S * S, MT = BATCH * M;
        const float* clsb = (const float*)d_in[5 * i + 2];
        const float* regb = (const float*)d_in[5 * i + 4];
        dim3 grid((Otot + 127) / 128, (MT + 127) / 128);
        gemm_kernel<<<grid, 256, SMEM>>>(XOFF[i], WOFF[i], regb, clsb, out,
                                         C, S, S, A, Otot, Ps[i], M);
    };

    // ncu profiles the 4th launch -> make it GEMM level 0
    prep(0);                    // 1, 2
    noop_kernel<<<1, 32>>>();   // 3
    gemm(0);                    // 4  <-- profiled
    for (int i = 1; i < 6; i++) prep(i);
    for (int i = 1; i < 6; i++) gemm(i);
}

// round 10
// speedup vs baseline: 6.0984x; 1.1897x over previous
#include <cuda_runtime.h>
#include <cuda_fp16.h>
#include <stdint.h>

#define BATCH 32
#define NPOS  8732
#define CLS_OFF ((size_t)BATCH * NPOS * 4)

// static scratch
__device__ __half g_xt[37412864];
__device__ __half g_wt[12695040];
__device__ float  g_bias[2850];

// per-level tables (L0..L5)
__constant__ int    c_cum[7]   = {0, 1083, 1538, 1663, 1698, 1707, 1710};
__constant__ int    c_ntO[6]   = {3, 5, 5, 5, 3, 3};
__constant__ int    c_C[6]     = {512, 1024, 512, 256, 256, 256};
__constant__ int    c_S[6]     = {38, 19, 10, 5, 3, 1};
__constant__ int    c_A[6]     = {4, 6, 6, 6, 4, 4};
__constant__ int    c_P[6]     = {0, 5776, 7942, 8542, 8692, 8728};
__constant__ int    c_boff[6]  = {0, 380, 950, 1520, 2090, 2470};
__constant__ size_t c_xoff[6]  = {0, 23658496, 35487744, 37126144, 37330944, 37404672};
__constant__ size_t c_woff[6]  = {0, 1751040, 7004160, 9630720, 10944000, 11819520};

__device__ __forceinline__ uint32_t smem_u32(const void* p) {
    uint32_t r;
    asm("{ .reg .u64 t; cvta.to.shared.u64 t, %1; cvt.u32.u64 %0, t; }" : "=r"(r) : "l"(p));
    return r;
}
__device__ __forceinline__ void cp16(uint32_t dst, const void* src, uint32_t sz) {
    asm volatile("cp.async.cg.shared.global [%0], [%1], 16, %2;"
                 :: "r"(dst), "l"(src), "r"(sz) : "memory");
}
__device__ __forceinline__ void cp_commit() { asm volatile("cp.async.commit_group;" ::: "memory"); }
__device__ __forceinline__ void cp_wait1()  { asm volatile("cp.async.wait_group 1;" ::: "memory"); }
__device__ __forceinline__ void ldsm4(uint32_t* r, uint32_t a) {
    asm volatile("ldmatrix.sync.aligned.m8n8.x4.shared.b16 {%0,%1,%2,%3}, [%4];"
                 : "=r"(r[0]), "=r"(r[1]), "=r"(r[2]), "=r"(r[3]) : "r"(a));
}
__device__ __forceinline__ void mma_f16(float* d, const uint32_t* a, uint32_t b0, uint32_t b1) {
    asm volatile("mma.sync.aligned.m16n8k16.row.col.f32.f16.f16.f32 "
                 "{%0,%1,%2,%3}, {%4,%5,%6,%7}, {%8,%9}, {%0,%1,%2,%3};"
                 : "+f"(d[0]), "+f"(d[1]), "+f"(d[2]), "+f"(d[3])
                 : "r"(a[0]), "r"(a[1]), "r"(a[2]), "r"(a[3]), "r"(b0), "r"(b1));
}

// ---- prep 1: activation transpose [n][c][p] -> [n][p][c], fp16 ----
__global__ void transpose_kernel(const float* __restrict__ x, size_t xoff, int C, int HW) {
    __shared__ float tile[32][33];
    const int n = blockIdx.z, p0 = blockIdx.x * 32, c0 = blockIdx.y * 32;
    const int tx = threadIdx.x, ty = threadIdx.y;
    const float* xb = x + (size_t)n * C * HW;
#pragma unroll
    for (int k = 0; k < 4; k++) {
        int c = c0 + ty + 8 * k, p = p0 + tx;
        tile[ty + 8 * k][tx] = (p < HW) ? xb[(size_t)c * HW + p] : 0.f;
    }
    __syncthreads();
#pragma unroll
    for (int k = 0; k < 4; k++) {
        int p = p0 + ty + 8 * k, c = c0 + tx;
        if (p < HW)
            g_xt[xoff + ((size_t)n * HW + p) * C + c] = __float2half_rn(tile[tx][ty + 8 * k]);
    }
}

// ---- prep 2: weights -> [tap][o][c] fp16 + combined bias ----
__global__ void pack_w_kernel(const float* __restrict__ regw, const float* __restrict__ clsw,
                              const float* __restrict__ regb, const float* __restrict__ clsb,
                              size_t woff, int boff, int C, int A4, int Otot) {
    int idx = blockIdx.x * blockDim.x + threadIdx.x;
    if (idx >= Otot * C) return;
    if (idx < Otot) g_bias[boff + idx] = (idx < A4) ? regb[idx] : clsb[idx - A4];
    int c = idx % C, o = idx / C;
    const float* src = (o < A4) ? (regw + ((size_t)o * C + c) * 9)
                                : (clsw + ((size_t)(o - A4) * C + c) * 9);
#pragma unroll
    for (int tap = 0; tap < 9; tap++)
        g_wt[woff + ((size_t)tap * Otot + o) * C + c] = __float2half_rn(src[tap]);
}

// ---- fused GEMM over ALL levels: fp16 m16n8k16, CTA 128x128, k-chunk 64 ----
#define ROWB 144
#define PLA  18432
#define STG  36864

__global__ __launch_bounds__(256, 2)
void gemm_kernel(float* __restrict__ out) {
    extern __shared__ char dsm[];
    const uint32_t sb = smem_u32(dsm);
    const int bid = blockIdx.x;

    int lvl = 0;
#pragma unroll
    for (int i = 1; i < 6; i++) if (bid >= c_cum[i]) lvl = i;
    const int C = c_C[lvl], H = c_S[lvl], W = H, A = c_A[lvl];
    const int Otot = 95 * A, P = c_P[lvl], M = H * W;
    const size_t xoff = c_xoff[lvl], woff = c_woff[lvl];
    const int boff = c_boff[lvl];
    const int tl = bid - c_cum[lvl];
    const int ntO = c_ntO[lvl];
    const int o0 = (tl % ntO) * 128, m0 = (tl / ntO) * 128;

    const int HW = M, KC = C >> 6, nchunks = 9 * KC;
    const int t = threadIdx.x, warp = t >> 5, lane = t & 31;
    const int MT = BATCH * M, A4 = 4 * A;
    const int mwarp = warp >> 2, nwarp = warp & 3;
    const int kofs = warp & 3;

    const int r = t >> 1, chalf = t & 1;
    const int ma = m0 + r;
    const bool avalid = (ma < MT);
    const int mm = avalid ? ma : 0;
    const int na = mm / M, pa = mm - na * M;
    const int ah_ = pa / W, aw_ = pa - ah_ * W;
    const size_t a_nbase = (size_t)na * HW * C;
    const int ob = o0 + r;
    const bool bvalid = (ob < Otot);
    const size_t b_obase = (size_t)(bvalid ? ob : 0) * C;
    const size_t OC = (size_t)Otot * C;
    const uint32_t dst_r = (uint32_t)r * ROWB + (uint32_t)chalf * 64;

    float acc[4][4][4];
#pragma unroll
    for (int i = 0; i < 4; i++)
#pragma unroll
        for (int j = 0; j < 4; j++)
#pragma unroll
            for (int k = 0; k < 4; k++) acc[i][j][k] = 0.f;

    const uint32_t a_lmrow = (uint32_t)(mwarp * 64 + (lane & 15)) * ROWB + ((lane >> 4) * 16);
    const int nl = (lane & 7) + ((lane >> 4) << 3);
    const uint32_t b_lmrow = (uint32_t)(nwarp * 32 + nl) * ROWB + (((lane >> 3) & 1) * 16);

#define LOAD_CHUNK(ch) {                                                            \
    const int s_ = (ch) % 3;                                                        \
    const int tap = (ch) / KC, ck = (ch) - tap * KC;                                \
    const int dy = tap / 3 - 1, dx = tap % 3 - 1;                                   \
    const int hh = ah_ + dy, ww = aw_ + dx;                                         \
    const bool aok = avalid && hh >= 0 && hh < H && ww >= 0 && ww < W;              \
    const size_t asrc = xoff + a_nbase + (size_t)(aok ? (hh * W + ww) : 0) * C      \
                        + (ck << 6) + chalf * 32;                                   \
    const size_t bsrc = woff + (size_t)tap * OC + b_obase + (ck << 6) + chalf * 32; \
    const uint32_t az = aok ? 16u : 0u, bz = bvalid ? 16u : 0u;                     \
    const uint32_t d0 = sb + s_ * STG + dst_r;                                      \
    _Pragma("unroll")                                                               \
    for (int c = 0; c < 4; c++) {                                                   \
        cp16(d0 + c * 16,       g_xt + asrc + c * 8, az);                           \
        cp16(d0 + PLA + c * 16, g_wt + bsrc + c * 8, bz);                           \
    }                                                                               \
    cp_commit(); }

    LOAD_CHUNK(0)
    LOAD_CHUNK(1)

    for (int ch = 0; ch < nchunks; ch++) {
        cp_wait1();
        __syncthreads();
        if (ch + 2 < nchunks) { LOAD_CHUNK(ch + 2) }
        else cp_commit();

        const uint32_t base = sb + (ch % 3) * STG;
#pragma unroll
        for (int ks4 = 0; ks4 < 4; ks4++) {
            const uint32_t ko = (uint32_t)((ks4 + kofs) & 3) * 32;
            uint32_t ah[4][4], bf[2][4];
#pragma unroll
            for (int mt = 0; mt < 4; mt++)
                ldsm4(ah[mt], base + a_lmrow + mt * (16 * ROWB) + ko);
#pragma unroll
            for (int bp = 0; bp < 2; bp++)
                ldsm4(bf[bp], base + PLA + b_lmrow + bp * (16 * ROWB) + ko);
#pragma unroll
            for (int mt = 0; mt < 4; mt++)
#pragma unroll
                for (int nt = 0; nt < 4; nt++) {
                    const int bp = nt >> 1, su = (nt & 1) * 2;
                    mma_f16(acc[mt][nt], ah[mt], bf[bp][su], bf[bp][su + 1]);
                }
        }
    }

    // ---- epilogue ----
    float* bbox = out;
    float* cls  = out + CLS_OFF;
#pragma unroll
    for (int mt = 0; mt < 4; mt++) {
#pragma unroll
        for (int half = 0; half < 2; half++) {
            const int m = m0 + mwarp * 64 + mt * 16 + (lane >> 2) + half * 8;
            if (m >= MT) continue;
            const int n = m / M, p = m - n * M;
            const size_t obase = (size_t)n * NPOS + P + (size_t)p * A;
#pragma unroll
            for (int nt = 0; nt < 4; nt++) {
#pragma unroll
                for (int e = 0; e < 2; e++) {
                    const int o = o0 + nwarp * 32 + nt * 8 + (lane & 3) * 2 + e;
                    if (o >= Otot) continue;
                    float v = acc[mt][nt][half * 2 + e] + g_bias[boff + o];
                    if (o < A4)
                        bbox[(obase + (o >> 2)) * 4 + (o & 3)] = v;
                    else {
                        const int q = o - A4;
                        const int a = q / 91;
                        cls[(obase + a) * 91 + (q - a * 91)] = v;
                    }
                }
            }
        }
    }
}

// ------------------------------- launch ------------------------------------
extern "C" void kernel_launch(void* const* d_in, const int* in_sizes, int n_in,
                              void* d_out, int out_size) {
    static const int    Cs[6]   = {512, 1024, 512, 256, 256, 256};
    static const int    Ss[6]   = {38, 19, 10, 5, 3, 1};
    static const int    Aa[6]   = {4, 6, 6, 6, 4, 4};
    static const int    BOFF[6] = {0, 380, 950, 1520, 2090, 2470};
    static const size_t XOFF[6] = {0, 23658496, 35487744, 37126144, 37330944, 37404672};
    static const size_t WOFF[6] = {0, 1751040, 7004160, 9630720, 10944000, 11819520};
    const int SMEM = 3 * STG;   // 110592

    cudaFuncSetAttribute(gemm_kernel, cudaFuncAttributeMaxDynamicSharedMemorySize, SMEM);
    float* out = (float*)d_out;

    for (int i = 0; i < 6; i++) {
        const int C = Cs[i], S = Ss[i], A = Aa[i];
        const int HW = S * S, Otot = 95 * A, A4 = 4 * A;
        const float* feat = (const float*)d_in[5 * i + 0];
        const float* clsw = (const float*)d_in[5 * i + 1];
        const float* clsb = (const float*)d_in[5 * i + 2];
        const float* regw = (const float*)d_in[5 * i + 3];
        const float* regb = (const float*)d_in[5 * i + 4];
        dim3 tg((HW + 31) / 32, C / 32, BATCH);
        transpose_kernel<<<tg, dim3(32, 8)>>>(feat, XOFF[i], C, HW);
        pack_w_kernel<<<(Otot * C + 255) / 256, 256>>>(regw, clsw, regb, clsb,
                                                       WOFF[i], BOFF[i], C, A4, Otot);
    }

    gemm_kernel<<<1710, 256, SMEM>>>(out);
}